// round 8
// baseline (speedup 1.0000x reference)
#include <cuda_runtime.h>

#define TPB 256

// shared-memory layout (float offsets) — weights only, ~138.5 KB
#define OFF_W11  0        // 128x8
#define OFF_B11  1024
#define OFF_W21  1152     // 128x8
#define OFF_B21  2176
#define OFF_W12  2304     // 128x128
#define OFF_B12  18688
#define OFF_W22  18816    // 128x128
#define OFF_B22  35200
#define OFF_WOUT 35328
#define SMEM_FLOATS 35456
#define SMEM_BYTES  (SMEM_FLOATS * 4)

using u64 = unsigned long long;

__device__ __forceinline__ u64 fma2(u64 a, u64 b, u64 c) {
    u64 d; asm("fma.rn.f32x2 %0, %1, %2, %3;" : "=l"(d) : "l"(a), "l"(b), "l"(c)); return d;
}
__device__ __forceinline__ u64 mul2(u64 a, u64 b) {
    u64 d; asm("mul.rn.f32x2 %0, %1, %2;" : "=l"(d) : "l"(a), "l"(b)); return d;
}
__device__ __forceinline__ u64 pack2(float lo, float hi) {
    u64 d; asm("mov.b64 %0, {%1, %2};" : "=l"(d) : "f"(lo), "f"(hi)); return d;
}
__device__ __forceinline__ float red2(u64 v) {
    float lo, hi; asm("mov.b64 {%0, %1}, %2;" : "=f"(lo), "=f"(hi) : "l"(v)); return lo + hi;
}
__device__ __forceinline__ float dot8(ulonglong2 w0, ulonglong2 w1,
                                      ulonglong2 xa, ulonglong2 xb) {
    u64 a = mul2(w0.x, xa.x);
    a = fma2(w0.y, xa.y, a);
    a = fma2(w1.x, xb.x, a);
    a = fma2(w1.y, xb.y, a);
    return red2(a);
}

__global__ __launch_bounds__(TPB, 1)
void net_kernel(const float* __restrict__ T, const float* __restrict__ L,
                const float* __restrict__ Ldot, const float* __restrict__ C,
                const float* __restrict__ w11, const float* __restrict__ b11,
                const float* __restrict__ w21, const float* __restrict__ b21,
                const float* __restrict__ w12, const float* __restrict__ b12,
                const float* __restrict__ w22, const float* __restrict__ b22,
                const float* __restrict__ wout, float* __restrict__ out)
{
    extern __shared__ float sm[];
    const int tid = threadIdx.x;

    // ---- cooperative weight load ----
    for (int i = tid; i < 1024; i += TPB) sm[OFF_W11 + i] = w11[i];
    for (int i = tid; i < 1024; i += TPB) sm[OFF_W21 + i] = w21[i];
    if (tid < 128) {
        sm[OFF_B11 + tid] = b11[tid];
        sm[OFF_B21 + tid] = b21[tid];
        sm[OFF_B12 + tid] = b12[tid];
        sm[OFF_B22 + tid] = b22[tid];
        sm[OFF_WOUT + tid] = wout[tid];
    }
    for (int i = tid * 4; i < 16384; i += TPB * 4)
        *reinterpret_cast<float4*>(&sm[OFF_W12 + i]) = *reinterpret_cast<const float4*>(&w12[i]);
    for (int i = tid * 4; i < 16384; i += TPB * 4)
        *reinterpret_cast<float4*>(&sm[OFF_W22 + i]) = *reinterpret_cast<const float4*>(&w22[i]);
    __syncthreads();

    const int bid = blockIdx.x;

    if (bid < 256 || bid >= 768) {
        // ========== forward-only (T or center), 2 samples/thread, 2 lanes/sample ==========
        const int p = tid & 1;        // hidden-half parity
        const int s = tid >> 1;       // sample slot (0..127)
        const float* wa  = &sm[OFF_W11 + p * 64 * 8];
        const float* wc  = &sm[OFF_W21 + p * 64 * 8];
        const float* sb1 = &sm[OFF_B11 + p * 64];
        const float* sb2 = &sm[OFF_B21 + p * 64];
        const float* w12p = &sm[OFF_W12 + p * 64];
        const float* w22p = &sm[OFF_W22 + p * 64];

        int idx0, obase;
        const float* base;
        if (bid < 256) { idx0 = bid * 256 + s; base = T; obase = 0; }
        else           { idx0 = (bid - 768) * 256 + s; base = C; obase = 196608; }
        int idx1 = idx0 + 128;

        const float* x0p = base + (size_t)idx0 * 8;
        const float* x1p = base + (size_t)idx1 * 8;
        ulonglong2 xa0 = *reinterpret_cast<const ulonglong2*>(x0p);
        ulonglong2 xb0 = *reinterpret_cast<const ulonglong2*>(x0p + 4);
        ulonglong2 xa1 = *reinterpret_cast<const ulonglong2*>(x1p);
        ulonglong2 xb1 = *reinterpret_cast<const ulonglong2*>(x1p + 4);

        // ---- layer 1: 64 hidden units, both samples share weight loads ----
        u64 y0[32], y1[32];
        float yp0 = 0.f, yp1 = 0.f;
        #pragma unroll
        for (int j = 0; j < 64; ++j) {
            const ulonglong2* ra = reinterpret_cast<const ulonglong2*>(wa + j * 8);
            const ulonglong2* rc = reinterpret_cast<const ulonglong2*>(wc + j * 8);
            ulonglong2 q0 = ra[0], q1 = ra[1];
            ulonglong2 m0 = rc[0], m1 = rc[1];
            float b1j = sb1[j], b2j = sb2[j];
            float z1_0 = dot8(q0, q1, xa0, xb0) + b1j;
            float z2_0 = dot8(m0, m1, xa0, xb0) + b2j;
            float z1_1 = dot8(q0, q1, xa1, xb1) + b1j;
            float z2_1 = dot8(m0, m1, xa1, xb1) + b2j;
            float yv0 = z1_0 * z2_0;
            float yv1 = z1_1 * z2_1;
            if (j & 1) { y0[j >> 1] = pack2(yp0, yv0); y1[j >> 1] = pack2(yp1, yv1); }
            else       { yp0 = yv0; yp1 = yv1; }
        }

        // ---- layer 2 + head ----
        float acc0 = 0.f, acc1 = 0.f;
        #pragma unroll 2
        for (int o = 0; o < 128; ++o) {
            const ulonglong2* r1 = reinterpret_cast<const ulonglong2*>(w12p + o * 128);
            const ulonglong2* r2 = reinterpret_cast<const ulonglong2*>(w22p + o * 128);
            u64 cA = 0, cB = 0, cC = 0, cD = 0;
            #pragma unroll
            for (int k = 0; k < 16; ++k) {
                ulonglong2 a = r1[k];
                ulonglong2 b = r2[k];
                u64 ya = y0[2 * k], yb = y0[2 * k + 1];
                u64 yc = y1[2 * k], yd = y1[2 * k + 1];
                cA = fma2(a.x, ya, cA);
                cB = fma2(b.x, ya, cB);
                cC = fma2(a.x, yc, cC);
                cD = fma2(b.x, yc, cD);
                cA = fma2(a.y, yb, cA);
                cB = fma2(b.y, yb, cB);
                cC = fma2(a.y, yd, cC);
                cD = fma2(b.y, yd, cD);
            }
            float u10 = red2(cA);
            float u20 = red2(cB);
            float u11 = red2(cC);
            float u21 = red2(cD);
            u10 += __shfl_xor_sync(0xffffffffu, u10, 1);
            u20 += __shfl_xor_sync(0xffffffffu, u20, 1);
            u11 += __shfl_xor_sync(0xffffffffu, u11, 1);
            u21 += __shfl_xor_sync(0xffffffffu, u21, 1);
            float bo1 = sm[OFF_B12 + o], bo2 = sm[OFF_B22 + o], wo = sm[OFF_WOUT + o];
            acc0 = fmaf(wo, (u10 + bo1) * (u20 + bo2), acc0);
            acc1 = fmaf(wo, (u11 + bo1) * (u21 + bo2), acc1);
        }
        if (p == 0) { out[obase + idx0] = acc0; out[obase + idx1] = acc1; }
    } else {
        // ========== l stream: fwd + JVP, 2 samples/thread, 4 lanes/sample ==========
        const int q = tid & 3;        // hidden quarter
        const int s = tid >> 2;       // sample slot (0..63)
        const float* wa  = &sm[OFF_W11 + q * 32 * 8];
        const float* wc  = &sm[OFF_W21 + q * 32 * 8];
        const float* sb1 = &sm[OFF_B11 + q * 32];
        const float* sb2 = &sm[OFF_B21 + q * 32];
        const float* w12q = &sm[OFF_W12 + q * 32];
        const float* w22q = &sm[OFF_W22 + q * 32];

        int lb = bid - 256;
        int idx0 = lb * 128 + s;
        int idx1 = idx0 + 64;
        const float* x0p = L + (size_t)idx0 * 8;
        const float* x1p = L + (size_t)idx1 * 8;
        const float* d0p = Ldot + (size_t)idx0 * 8;
        const float* d1p = Ldot + (size_t)idx1 * 8;
        ulonglong2 xa0 = *reinterpret_cast<const ulonglong2*>(x0p);
        ulonglong2 xb0 = *reinterpret_cast<const ulonglong2*>(x0p + 4);
        ulonglong2 xa1 = *reinterpret_cast<const ulonglong2*>(x1p);
        ulonglong2 xb1 = *reinterpret_cast<const ulonglong2*>(x1p + 4);
        ulonglong2 da0 = *reinterpret_cast<const ulonglong2*>(d0p);
        ulonglong2 db0 = *reinterpret_cast<const ulonglong2*>(d0p + 4);
        ulonglong2 da1 = *reinterpret_cast<const ulonglong2*>(d1p);
        ulonglong2 db1 = *reinterpret_cast<const ulonglong2*>(d1p + 4);

        // ---- layer 1: 32 hidden units per thread, y + yd for both samples ----
        u64 y0[16], g0[16], y1[16], g1[16];
        float yp0 = 0.f, gp0 = 0.f, yp1 = 0.f, gp1 = 0.f;
        #pragma unroll
        for (int j = 0; j < 32; ++j) {
            const ulonglong2* ra = reinterpret_cast<const ulonglong2*>(wa + j * 8);
            const ulonglong2* rc = reinterpret_cast<const ulonglong2*>(wc + j * 8);
            ulonglong2 q0 = ra[0], q1 = ra[1];
            ulonglong2 m0 = rc[0], m1 = rc[1];
            float b1j = sb1[j], b2j = sb2[j];
            float z1_0  = dot8(q0, q1, xa0, xb0) + b1j;
            float z2_0  = dot8(m0, m1, xa0, xb0) + b2j;
            float z1d_0 = dot8(q0, q1, da0, db0);
            float z2d_0 = dot8(m0, m1, da0, db0);
            float z1_1  = dot8(q0, q1, xa1, xb1) + b1j;
            float z2_1  = dot8(m0, m1, xa1, xb1) + b2j;
            float z1d_1 = dot8(q0, q1, da1, db1);
            float z2d_1 = dot8(m0, m1, da1, db1);
            float yv0 = z1_0 * z2_0;
            float gv0 = fmaf(z1d_0, z2_0, z1_0 * z2d_0);
            float yv1 = z1_1 * z2_1;
            float gv1 = fmaf(z1d_1, z2_1, z1_1 * z2d_1);
            if (j & 1) {
                y0[j >> 1] = pack2(yp0, yv0); g0[j >> 1] = pack2(gp0, gv0);
                y1[j >> 1] = pack2(yp1, yv1); g1[j >> 1] = pack2(gp1, gv1);
            } else { yp0 = yv0; gp0 = gv0; yp1 = yv1; gp1 = gv1; }
        }

        // ---- layer 2 + head (value + JVP) ----
        float vacc0 = 0.f, gacc0 = 0.f, vacc1 = 0.f, gacc1 = 0.f;
        #pragma unroll 2
        for (int o = 0; o < 128; ++o) {
            const ulonglong2* r1 = reinterpret_cast<const ulonglong2*>(w12q + o * 128);
            const ulonglong2* r2 = reinterpret_cast<const ulonglong2*>(w22q + o * 128);
            u64 c10 = 0, c20 = 0, e10 = 0, e20 = 0;
            u64 c11 = 0, c21 = 0, e11 = 0, e21 = 0;
            #pragma unroll
            for (int k = 0; k < 8; ++k) {
                ulonglong2 a = r1[k];
                ulonglong2 b = r2[k];
                u64 ya = y0[2 * k], yb = y0[2 * k + 1];
                u64 ga = g0[2 * k], gb = g0[2 * k + 1];
                u64 yc = y1[2 * k], yd = y1[2 * k + 1];
                u64 gc = g1[2 * k], gd = g1[2 * k + 1];
                c10 = fma2(a.x, ya, c10);
                c20 = fma2(b.x, ya, c20);
                e10 = fma2(a.x, ga, e10);
                e20 = fma2(b.x, ga, e20);
                c11 = fma2(a.x, yc, c11);
                c21 = fma2(b.x, yc, c21);
                e11 = fma2(a.x, gc, e11);
                e21 = fma2(b.x, gc, e21);
                c10 = fma2(a.y, yb, c10);
                c20 = fma2(b.y, yb, c20);
                e10 = fma2(a.y, gb, e10);
                e20 = fma2(b.y, gb, e20);
                c11 = fma2(a.y, yd, c11);
                c21 = fma2(b.y, yd, c21);
                e11 = fma2(a.y, gd, e11);
                e21 = fma2(b.y, gd, e21);
            }
            float u10  = red2(c10), u20  = red2(c20);
            float u1d0 = red2(e10), u2d0 = red2(e20);
            float u11  = red2(c11), u21  = red2(c21);
            float u1d1 = red2(e11), u2d1 = red2(e21);
            u10  += __shfl_xor_sync(0xffffffffu, u10, 1);
            u20  += __shfl_xor_sync(0xffffffffu, u20, 1);
            u1d0 += __shfl_xor_sync(0xffffffffu, u1d0, 1);
            u2d0 += __shfl_xor_sync(0xffffffffu, u2d0, 1);
            u11  += __shfl_xor_sync(0xffffffffu, u11, 1);
            u21  += __shfl_xor_sync(0xffffffffu, u21, 1);
            u1d1 += __shfl_xor_sync(0xffffffffu, u1d1, 1);
            u2d1 += __shfl_xor_sync(0xffffffffu, u2d1, 1);
            u10  += __shfl_xor_sync(0xffffffffu, u10, 2);
            u20  += __shfl_xor_sync(0xffffffffu, u20, 2);
            u1d0 += __shfl_xor_sync(0xffffffffu, u1d0, 2);
            u2d0 += __shfl_xor_sync(0xffffffffu, u2d0, 2);
            u11  += __shfl_xor_sync(0xffffffffu, u11, 2);
            u21  += __shfl_xor_sync(0xffffffffu, u21, 2);
            u1d1 += __shfl_xor_sync(0xffffffffu, u1d1, 2);
            u2d1 += __shfl_xor_sync(0xffffffffu, u2d1, 2);
            float bo1 = sm[OFF_B12 + o], bo2 = sm[OFF_B22 + o], wo = sm[OFF_WOUT + o];
            float a10 = u10 + bo1, a20 = u20 + bo2;
            float a11 = u11 + bo1, a21 = u21 + bo2;
            vacc0 = fmaf(wo, a10 * a20, vacc0);
            gacc0 = fmaf(wo, fmaf(u1d0, a20, a10 * u2d0), gacc0);
            vacc1 = fmaf(wo, a11 * a21, vacc1);
            gacc1 = fmaf(wo, fmaf(u1d1, a21, a11 * u2d1), gacc1);
        }
        if (q == 0) {
            out[65536 + idx0]  = vacc0;
            out[131072 + idx0] = gacc0;
            out[65536 + idx1]  = vacc1;
            out[131072 + idx1] = gacc1;
        }
    }
}

extern "C" void kernel_launch(void* const* d_in, const int* in_sizes, int n_in,
                              void* d_out, int out_size)
{
    const float* T    = (const float*)d_in[0];
    const float* L    = (const float*)d_in[1];
    const float* Ldot = (const float*)d_in[2];
    const float* C    = (const float*)d_in[3];
    const float* w11  = (const float*)d_in[4];
    const float* b11  = (const float*)d_in[5];
    const float* w21  = (const float*)d_in[6];
    const float* b21  = (const float*)d_in[7];
    const float* w12  = (const float*)d_in[8];
    const float* b12  = (const float*)d_in[9];
    const float* w22  = (const float*)d_in[10];
    const float* b22  = (const float*)d_in[11];
    const float* wout = (const float*)d_in[12];
    float* out = (float*)d_out;

    cudaFuncSetAttribute(net_kernel, cudaFuncAttributeMaxDynamicSharedMemorySize, SMEM_BYTES);

    // blocks: [0,256) -> T (256 samples each), [256,768) -> l (128 samples each),
    //         [768,770) -> center (256 samples each)
    net_kernel<<<770, TPB, SMEM_BYTES>>>(T, L, Ldot, C,
                                         w11, b11, w21, b21,
                                         w12, b12, w22, b22,
                                         wout, out);
}

// round 10
// speedup vs baseline: 2.3807x; 2.3807x over previous
#include <cuda_runtime.h>

#define TPB 512

// shared-memory layout (float offsets)
#define OFF_W11   0        // 128x8 row-major
#define OFF_B11   1024
#define OFF_W21   1152     // 128x8
#define OFF_B21   2176
#define OFF_W12T  2304     // 128x128 TRANSPOSED: [k][o]
#define OFF_B12   18688
#define OFF_W22T  18816    // 128x128 TRANSPOSED: [k][o]
#define OFF_B22   35200
#define OFF_WOUT  35328
#define OFF_Y     35456    // fwd: 128x128 [k][s] ; l: 128x64 [k][s]
#define OFF_YD    43648    // l only: 128x64 [k][s]
#define OFF_SCR   51840    // 256 floats cross-warp scratch
#define SMEM_FLOATS 52096
#define SMEM_BYTES  (SMEM_FLOATS * 4)

using u64 = unsigned long long;

__device__ __forceinline__ u64 fma2(u64 a, u64 b, u64 c) {
    u64 d; asm("fma.rn.f32x2 %0, %1, %2, %3;" : "=l"(d) : "l"(a), "l"(b), "l"(c)); return d;
}
__device__ __forceinline__ u64 mul2(u64 a, u64 b) {
    u64 d; asm("mul.rn.f32x2 %0, %1, %2;" : "=l"(d) : "l"(a), "l"(b)); return d;
}
__device__ __forceinline__ u64 dup2(float f) {
    u64 d; asm("mov.b64 %0, {%1, %1};" : "=l"(d) : "f"(f)); return d;
}
__device__ __forceinline__ void unpack2(u64 v, float& lo, float& hi) {
    asm("mov.b64 {%0, %1}, %2;" : "=f"(lo), "=f"(hi) : "l"(v));
}
__device__ __forceinline__ float red2(u64 v) {
    float lo, hi; unpack2(v, lo, hi); return lo + hi;
}
__device__ __forceinline__ float dot8(ulonglong2 w0, ulonglong2 w1,
                                      ulonglong2 xa, ulonglong2 xb) {
    u64 a = mul2(w0.x, xa.x);
    a = fma2(w0.y, xa.y, a);
    a = fma2(w1.x, xb.x, a);
    a = fma2(w1.y, xb.y, a);
    return red2(a);
}

__global__ __launch_bounds__(TPB, 1)
void net_kernel(const float* __restrict__ T, const float* __restrict__ L,
                const float* __restrict__ Ldot, const float* __restrict__ C,
                const float* __restrict__ w11, const float* __restrict__ b11,
                const float* __restrict__ w21, const float* __restrict__ b21,
                const float* __restrict__ w12, const float* __restrict__ b12,
                const float* __restrict__ w22, const float* __restrict__ b22,
                const float* __restrict__ wout, float* __restrict__ out)
{
    extern __shared__ float sm[];
    const int tid = threadIdx.x;

    // ---- weight staging ----
    for (int i = tid; i < 1024; i += TPB) sm[OFF_W11 + i] = w11[i];
    for (int i = tid; i < 1024; i += TPB) sm[OFF_W21 + i] = w21[i];
    if (tid < 128) {
        sm[OFF_B11 + tid] = b11[tid];
        sm[OFF_B21 + tid] = b21[tid];
        sm[OFF_B12 + tid] = b12[tid];
        sm[OFF_B22 + tid] = b22[tid];
        sm[OFF_WOUT + tid] = wout[tid];
    }
    // transpose W12, W22 into [k][o]
    {
        int o = tid & 127;
        int kq = tid >> 7;          // 0..3
        for (int kb = kq; kb < 32; kb += 4) {
            float4 v = *reinterpret_cast<const float4*>(&w12[o * 128 + kb * 4]);
            sm[OFF_W12T + (kb * 4 + 0) * 128 + o] = v.x;
            sm[OFF_W12T + (kb * 4 + 1) * 128 + o] = v.y;
            sm[OFF_W12T + (kb * 4 + 2) * 128 + o] = v.z;
            sm[OFF_W12T + (kb * 4 + 3) * 128 + o] = v.w;
            float4 u = *reinterpret_cast<const float4*>(&w22[o * 128 + kb * 4]);
            sm[OFF_W22T + (kb * 4 + 0) * 128 + o] = u.x;
            sm[OFF_W22T + (kb * 4 + 1) * 128 + o] = u.y;
            sm[OFF_W22T + (kb * 4 + 2) * 128 + o] = u.z;
            sm[OFF_W22T + (kb * 4 + 3) * 128 + o] = u.w;
        }
    }
    __syncthreads();

    const int bid = blockIdx.x;

    if (bid < 256 || bid >= 768) {
        // =================== forward-only blocks (T / center) ===================
        const float* base = (bid < 256) ? T : C;
        const int obase   = (bid < 256) ? 0 : 196608;
        const int btile   = (bid < 256) ? bid : (bid - 768);

        for (int g = 0; g < 2; ++g) {
            const int sbase = (btile * 2 + g) * 128;

            // ---- phase 1: layer 1 -> y in shared [k][128], 4 threads/sample ----
            {
                const int s = tid & 127;
                const int q = tid >> 7;              // hidden quarter
                const float* xp = base + (size_t)(sbase + s) * 8;
                ulonglong2 xa = *reinterpret_cast<const ulonglong2*>(xp);
                ulonglong2 xb = *reinterpret_cast<const ulonglong2*>(xp + 4);
                #pragma unroll
                for (int j = 0; j < 32; ++j) {
                    int r = q * 32 + j;
                    const ulonglong2* ra = reinterpret_cast<const ulonglong2*>(&sm[OFF_W11 + r * 8]);
                    const ulonglong2* rc = reinterpret_cast<const ulonglong2*>(&sm[OFF_W21 + r * 8]);
                    float z1 = dot8(ra[0], ra[1], xa, xb) + sm[OFF_B11 + r];
                    float z2 = dot8(rc[0], rc[1], xa, xb) + sm[OFF_B21 + r];
                    sm[OFF_Y + r * 128 + s] = z1 * z2;
                }
            }
            __syncthreads();

            // ---- phase 2: GEMM, thread tile = 8 samples x 4 outputs x 2 mats ----
            {
                const int ot = tid & 31;             // o-tile (4 outputs)
                const int st = tid >> 5;             // s-tile (8 samples)
                const int s0 = st * 8;
                const int ot4 = ot * 4;

                u64 A1[16], A2[16];
                #pragma unroll
                for (int i = 0; i < 16; ++i) { A1[i] = 0; A2[i] = 0; }

                #pragma unroll 2
                for (int k = 0; k < 128; ++k) {
                    ulonglong2 yA = *reinterpret_cast<const ulonglong2*>(&sm[OFF_Y + k * 128 + s0]);
                    ulonglong2 yB = *reinterpret_cast<const ulonglong2*>(&sm[OFF_Y + k * 128 + s0 + 4]);
                    float4 w1 = *reinterpret_cast<const float4*>(&sm[OFF_W12T + k * 128 + ot4]);
                    float4 w2 = *reinterpret_cast<const float4*>(&sm[OFF_W22T + k * 128 + ot4]);
                    float w1a[4] = {w1.x, w1.y, w1.z, w1.w};
                    float w2a[4] = {w2.x, w2.y, w2.z, w2.w};
                    #pragma unroll
                    for (int o = 0; o < 4; ++o) {
                        u64 d1 = dup2(w1a[o]);
                        u64 d2 = dup2(w2a[o]);
                        A1[o * 4 + 0] = fma2(d1, yA.x, A1[o * 4 + 0]);
                        A2[o * 4 + 0] = fma2(d2, yA.x, A2[o * 4 + 0]);
                        A1[o * 4 + 1] = fma2(d1, yA.y, A1[o * 4 + 1]);
                        A2[o * 4 + 1] = fma2(d2, yA.y, A2[o * 4 + 1]);
                        A1[o * 4 + 2] = fma2(d1, yB.x, A1[o * 4 + 2]);
                        A2[o * 4 + 2] = fma2(d2, yB.x, A2[o * 4 + 2]);
                        A1[o * 4 + 3] = fma2(d1, yB.y, A1[o * 4 + 3]);
                        A2[o * 4 + 3] = fma2(d2, yB.y, A2[o * 4 + 3]);
                    }
                }

                // epilogue: head dot, warp-reduce over the 32 o-tiles
                float part[8] = {0.f, 0.f, 0.f, 0.f, 0.f, 0.f, 0.f, 0.f};
                #pragma unroll
                for (int o = 0; o < 4; ++o) {
                    int og = ot4 + o;
                    float bo1 = sm[OFF_B12 + og], bo2 = sm[OFF_B22 + og], wo = sm[OFF_WOUT + og];
                    #pragma unroll
                    for (int sp = 0; sp < 4; ++sp) {
                        float u1l, u1h, u2l, u2h;
                        unpack2(A1[o * 4 + sp], u1l, u1h);
                        unpack2(A2[o * 4 + sp], u2l, u2h);
                        part[sp * 2]     = fmaf(wo, (u1l + bo1) * (u2l + bo2), part[sp * 2]);
                        part[sp * 2 + 1] = fmaf(wo, (u1h + bo1) * (u2h + bo2), part[sp * 2 + 1]);
                    }
                }
                #pragma unroll
                for (int i = 0; i < 8; ++i) {
                    #pragma unroll
                    for (int m = 16; m > 0; m >>= 1)
                        part[i] += __shfl_xor_sync(0xffffffffu, part[i], m);
                }
                if ((tid & 31) == 0) {
                    #pragma unroll
                    for (int i = 0; i < 8; ++i)
                        out[obase + sbase + s0 + i] = part[i];
                }
            }
            __syncthreads();
        }
    } else {
        // =================== l blocks: forward + JVP ===================
        const int lb = bid - 256;
        for (int g = 0; g < 2; ++g) {
            const int sbase = (lb * 2 + g) * 64;

            // ---- phase 1: layer 1 -> y, yd in shared [k][64], 8 threads/sample ----
            {
                const int s = tid & 63;
                const int p = tid >> 6;              // 0..7, 16 rows each
                const float* xp = L    + (size_t)(sbase + s) * 8;
                const float* dp = Ldot + (size_t)(sbase + s) * 8;
                ulonglong2 xa = *reinterpret_cast<const ulonglong2*>(xp);
                ulonglong2 xb = *reinterpret_cast<const ulonglong2*>(xp + 4);
                ulonglong2 da = *reinterpret_cast<const ulonglong2*>(dp);
                ulonglong2 db = *reinterpret_cast<const ulonglong2*>(dp + 4);
                #pragma unroll
                for (int j = 0; j < 16; ++j) {
                    int r = p * 16 + j;
                    const ulonglong2* ra = reinterpret_cast<const ulonglong2*>(&sm[OFF_W11 + r * 8]);
                    const ulonglong2* rc = reinterpret_cast<const ulonglong2*>(&sm[OFF_W21 + r * 8]);
                    ulonglong2 q0 = ra[0], q1 = ra[1];
                    ulonglong2 m0 = rc[0], m1 = rc[1];
                    float z1  = dot8(q0, q1, xa, xb) + sm[OFF_B11 + r];
                    float z2  = dot8(m0, m1, xa, xb) + sm[OFF_B21 + r];
                    float z1d = dot8(q0, q1, da, db);
                    float z2d = dot8(m0, m1, da, db);
                    sm[OFF_Y  + r * 64 + s] = z1 * z2;
                    sm[OFF_YD + r * 64 + s] = fmaf(z1d, z2, z1 * z2d);
                }
            }
            __syncthreads();

            // ---- phase 2: 4 GEMM accum sets, tile = 8 samples x 2 outputs ----
            {
                const int ot = tid & 63;             // o-tile (2 outputs)
                const int st = tid >> 6;             // s-tile (8 samples)
                const int s0 = st * 8;
                const int ot2 = ot * 2;

                u64 C1[8], C2[8], E1[8], E2[8];
                #pragma unroll
                for (int i = 0; i < 8; ++i) { C1[i] = 0; C2[i] = 0; E1[i] = 0; E2[i] = 0; }

                #pragma unroll 2
                for (int k = 0; k < 128; ++k) {
                    ulonglong2 yA = *reinterpret_cast<const ulonglong2*>(&sm[OFF_Y  + k * 64 + s0]);
                    ulonglong2 yB = *reinterpret_cast<const ulonglong2*>(&sm[OFF_Y  + k * 64 + s0 + 4]);
                    ulonglong2 gA = *reinterpret_cast<const ulonglong2*>(&sm[OFF_YD + k * 64 + s0]);
                    ulonglong2 gB = *reinterpret_cast<const ulonglong2*>(&sm[OFF_YD + k * 64 + s0 + 4]);
                    float2 w1 = *reinterpret_cast<const float2*>(&sm[OFF_W12T + k * 128 + ot2]);
                    float2 w2 = *reinterpret_cast<const float2*>(&sm[OFF_W22T + k * 128 + ot2]);
                    float w1a[2] = {w1.x, w1.y};
                    float w2a[2] = {w2.x, w2.y};
                    #pragma unroll
                    for (int o = 0; o < 2; ++o) {
                        u64 d1 = dup2(w1a[o]);
                        u64 d2 = dup2(w2a[o]);
                        C1[o * 4 + 0] = fma2(d1, yA.x, C1[o * 4 + 0]);
                        C2[o * 4 + 0] = fma2(d2, yA.x, C2[o * 4 + 0]);
                        E1[o * 4 + 0] = fma2(d1, gA.x, E1[o * 4 + 0]);
                        E2[o * 4 + 0] = fma2(d2, gA.x, E2[o * 4 + 0]);
                        C1[o * 4 + 1] = fma2(d1, yA.y, C1[o * 4 + 1]);
                        C2[o * 4 + 1] = fma2(d2, yA.y, C2[o * 4 + 1]);
                        E1[o * 4 + 1] = fma2(d1, gA.y, E1[o * 4 + 1]);
                        E2[o * 4 + 1] = fma2(d2, gA.y, E2[o * 4 + 1]);
                        C1[o * 4 + 2] = fma2(d1, yB.x, C1[o * 4 + 2]);
                        C2[o * 4 + 2] = fma2(d2, yB.x, C2[o * 4 + 2]);
                        E1[o * 4 + 2] = fma2(d1, gB.x, E1[o * 4 + 2]);
                        E2[o * 4 + 2] = fma2(d2, gB.x, E2[o * 4 + 2]);
                        C1[o * 4 + 3] = fma2(d1, yB.y, C1[o * 4 + 3]);
                        C2[o * 4 + 3] = fma2(d2, yB.y, C2[o * 4 + 3]);
                        E1[o * 4 + 3] = fma2(d1, gB.y, E1[o * 4 + 3]);
                        E2[o * 4 + 3] = fma2(d2, gB.y, E2[o * 4 + 3]);
                    }
                }

                float vp[8] = {0.f, 0.f, 0.f, 0.f, 0.f, 0.f, 0.f, 0.f};
                float gp[8] = {0.f, 0.f, 0.f, 0.f, 0.f, 0.f, 0.f, 0.f};
                #pragma unroll
                for (int o = 0; o < 2; ++o) {
                    int og = ot2 + o;
                    float bo1 = sm[OFF_B12 + og], bo2 = sm[OFF_B22 + og], wo = sm[OFF_WOUT + og];
                    #pragma unroll
                    for (int sp = 0; sp < 4; ++sp) {
                        float u1l, u1h, u2l, u2h, d1l, d1h, d2l, d2h;
                        unpack2(C1[o * 4 + sp], u1l, u1h);
                        unpack2(C2[o * 4 + sp], u2l, u2h);
                        unpack2(E1[o * 4 + sp], d1l, d1h);
                        unpack2(E2[o * 4 + sp], d2l, d2h);
                        float a1l = u1l + bo1, a2l = u2l + bo2;
                        float a1h = u1h + bo1, a2h = u2h + bo2;
                        vp[sp * 2]     = fmaf(wo, a1l * a2l, vp[sp * 2]);
                        gp[sp * 2]     = fmaf(wo, fmaf(d1l, a2l, a1l * d2l), gp[sp * 2]);
                        vp[sp * 2 + 1] = fmaf(wo, a1h * a2h, vp[sp * 2 + 1]);
                        gp[sp * 2 + 1] = fmaf(wo, fmaf(d1h, a2h, a1h * d2h), gp[sp * 2 + 1]);
                    }
                }
                #pragma unroll
                for (int i = 0; i < 8; ++i) {
                    #pragma unroll
                    for (int m = 16; m > 0; m >>= 1) {
                        vp[i] += __shfl_xor_sync(0xffffffffu, vp[i], m);
                        gp[i] += __shfl_xor_sync(0xffffffffu, gp[i], m);
                    }
                }
                // two warps share each s-tile: stage per-warp sums, then combine
                if ((tid & 31) == 0) {
                    int half = (tid >> 5) & 1;       // which o-half this warp covered
                    float* scr = &sm[OFF_SCR + half * 128 + st * 16];
                    #pragma unroll
                    for (int i = 0; i < 8; ++i) { scr[i] = vp[i]; scr[8 + i] = gp[i]; }
                }
            }
            __syncthreads();
            if (tid < 128) {
                int st2 = tid >> 4, i = tid & 15;
                float v = sm[OFF_SCR + st2 * 16 + i] + sm[OFF_SCR + 128 + st2 * 16 + i];
                int sample = sbase + st2 * 8 + (i & 7);
                out[(i < 8 ? 65536 : 131072) + sample] = v;
            }
            __syncthreads();
        }
    }
}

extern "C" void kernel_launch(void* const* d_in, const int* in_sizes, int n_in,
                              void* d_out, int out_size)
{
    const float* T    = (const float*)d_in[0];
    const float* L    = (const float*)d_in[1];
    const float* Ldot = (const float*)d_in[2];
    const float* C    = (const float*)d_in[3];
    const float* w11  = (const float*)d_in[4];
    const float* b11  = (const float*)d_in[5];
    const float* w21  = (const float*)d_in[6];
    const float* b21  = (const float*)d_in[7];
    const float* w12  = (const float*)d_in[8];
    const float* b12  = (const float*)d_in[9];
    const float* w22  = (const float*)d_in[10];
    const float* b22  = (const float*)d_in[11];
    const float* wout = (const float*)d_in[12];
    float* out = (float*)d_out;

    cudaFuncSetAttribute(net_kernel, cudaFuncAttributeMaxDynamicSharedMemorySize, SMEM_BYTES);

    // blocks: [0,256) -> T (2x128 samples), [256,768) -> l (2x64 samples),
    //         [768,770) -> center (2x128 samples)
    net_kernel<<<770, TPB, SMEM_BYTES>>>(T, L, Ldot, C,
                                         w11, b11, w21, b21,
                                         w12, b12, w22, b22,
                                         wout, out);
}

// round 11
// speedup vs baseline: 2.7955x; 1.1742x over previous
#include <cuda_runtime.h>

#define TPB 512
#define NBLOCKS 148
#define N_UNITS 1540   // 512 fwd-T + 1024 l + 4 center

// shared-memory layout (float offsets)
#define OFF_W11   0        // 128x8 row-major
#define OFF_B11   1024
#define OFF_W21   1152     // 128x8
#define OFF_B21   2176
#define OFF_W12T  2304     // 128x128 TRANSPOSED: [k][o]
#define OFF_B12   18688
#define OFF_W22T  18816    // 128x128 TRANSPOSED: [k][o]
#define OFF_B22   35200
#define OFF_WOUT  35328
#define OFF_Y     35456    // fwd: 128x128 [k][s] ; l: 128x64 [k][s]
#define OFF_YD    43648    // l only: 128x64 [k][s]
#define OFF_SCR   51840    // 256 floats cross-warp scratch
#define SMEM_FLOATS 52096
#define SMEM_BYTES  (SMEM_FLOATS * 4)

using u64 = unsigned long long;

__device__ __forceinline__ u64 fma2(u64 a, u64 b, u64 c) {
    u64 d; asm("fma.rn.f32x2 %0, %1, %2, %3;" : "=l"(d) : "l"(a), "l"(b), "l"(c)); return d;
}
__device__ __forceinline__ u64 mul2(u64 a, u64 b) {
    u64 d; asm("mul.rn.f32x2 %0, %1, %2;" : "=l"(d) : "l"(a), "l"(b)); return d;
}
__device__ __forceinline__ u64 dup2(float f) {
    u64 d; asm("mov.b64 %0, {%1, %1};" : "=l"(d) : "f"(f)); return d;
}
__device__ __forceinline__ void unpack2(u64 v, float& lo, float& hi) {
    asm("mov.b64 {%0, %1}, %2;" : "=f"(lo), "=f"(hi) : "l"(v));
}
__device__ __forceinline__ float red2(u64 v) {
    float lo, hi; unpack2(v, lo, hi); return lo + hi;
}
__device__ __forceinline__ float dot8(ulonglong2 w0, ulonglong2 w1,
                                      ulonglong2 xa, ulonglong2 xb) {
    u64 a = mul2(w0.x, xa.x);
    a = fma2(w0.y, xa.y, a);
    a = fma2(w1.x, xb.x, a);
    a = fma2(w1.y, xb.y, a);
    return red2(a);
}

__global__ __launch_bounds__(TPB, 1)
void net_kernel(const float* __restrict__ T, const float* __restrict__ L,
                const float* __restrict__ Ldot, const float* __restrict__ C,
                const float* __restrict__ w11, const float* __restrict__ b11,
                const float* __restrict__ w21, const float* __restrict__ b21,
                const float* __restrict__ w12, const float* __restrict__ b12,
                const float* __restrict__ w22, const float* __restrict__ b22,
                const float* __restrict__ wout, float* __restrict__ out)
{
    extern __shared__ float sm[];
    const int tid = threadIdx.x;

    // ---- weight staging (once per block = once per SM) ----
    for (int i = tid; i < 1024; i += TPB) sm[OFF_W11 + i] = w11[i];
    for (int i = tid; i < 1024; i += TPB) sm[OFF_W21 + i] = w21[i];
    if (tid < 128) {
        sm[OFF_B11 + tid] = b11[tid];
        sm[OFF_B21 + tid] = b21[tid];
        sm[OFF_B12 + tid] = b12[tid];
        sm[OFF_B22 + tid] = b22[tid];
        sm[OFF_WOUT + tid] = wout[tid];
    }
    // transpose W12, W22 into [k][o]
    {
        int o = tid & 127;
        int kq = tid >> 7;          // 0..3
        for (int kb = kq; kb < 32; kb += 4) {
            float4 v = *reinterpret_cast<const float4*>(&w12[o * 128 + kb * 4]);
            sm[OFF_W12T + (kb * 4 + 0) * 128 + o] = v.x;
            sm[OFF_W12T + (kb * 4 + 1) * 128 + o] = v.y;
            sm[OFF_W12T + (kb * 4 + 2) * 128 + o] = v.z;
            sm[OFF_W12T + (kb * 4 + 3) * 128 + o] = v.w;
            float4 u = *reinterpret_cast<const float4*>(&w22[o * 128 + kb * 4]);
            sm[OFF_W22T + (kb * 4 + 0) * 128 + o] = u.x;
            sm[OFF_W22T + (kb * 4 + 1) * 128 + o] = u.y;
            sm[OFF_W22T + (kb * 4 + 2) * 128 + o] = u.z;
            sm[OFF_W22T + (kb * 4 + 3) * 128 + o] = u.w;
        }
    }
    __syncthreads();

    // ---- persistent unit loop ----
    // units: [0,512) fwd on T (128 samples), [512,1536) l (64 samples),
    //        [1536,1540) fwd on center (128 samples)
    for (int u = blockIdx.x; u < N_UNITS; u += NBLOCKS) {
        if (u < 512 || u >= 1536) {
            // =================== forward-only unit (T / center) ===================
            const float* base = (u < 512) ? T : C;
            const int obase   = (u < 512) ? 0 : 196608;
            const int sbase   = (u < 512) ? u * 128 : (u - 1536) * 128;

            // ---- phase 1: layer 1 -> y in shared [k][128], 4 threads/sample ----
            {
                const int s = tid & 127;
                const int q = tid >> 7;              // hidden quarter
                const float* xp = base + (size_t)(sbase + s) * 8;
                ulonglong2 xa = *reinterpret_cast<const ulonglong2*>(xp);
                ulonglong2 xb = *reinterpret_cast<const ulonglong2*>(xp + 4);
                #pragma unroll
                for (int j = 0; j < 32; ++j) {
                    int r = q * 32 + j;
                    const ulonglong2* ra = reinterpret_cast<const ulonglong2*>(&sm[OFF_W11 + r * 8]);
                    const ulonglong2* rc = reinterpret_cast<const ulonglong2*>(&sm[OFF_W21 + r * 8]);
                    float z1 = dot8(ra[0], ra[1], xa, xb) + sm[OFF_B11 + r];
                    float z2 = dot8(rc[0], rc[1], xa, xb) + sm[OFF_B21 + r];
                    sm[OFF_Y + r * 128 + s] = z1 * z2;
                }
            }
            __syncthreads();

            // ---- phase 2: GEMM, thread tile = 8 samples x 4 outputs x 2 mats ----
            {
                const int ot = tid & 31;             // o-tile (4 outputs)
                const int st = tid >> 5;             // s-tile (8 samples)
                const int s0 = st * 8;
                const int ot4 = ot * 4;

                u64 A1[16], A2[16];
                #pragma unroll
                for (int i = 0; i < 16; ++i) { A1[i] = 0; A2[i] = 0; }

                #pragma unroll 2
                for (int k = 0; k < 128; ++k) {
                    ulonglong2 yA = *reinterpret_cast<const ulonglong2*>(&sm[OFF_Y + k * 128 + s0]);
                    ulonglong2 yB = *reinterpret_cast<const ulonglong2*>(&sm[OFF_Y + k * 128 + s0 + 4]);
                    float4 w1 = *reinterpret_cast<const float4*>(&sm[OFF_W12T + k * 128 + ot4]);
                    float4 w2 = *reinterpret_cast<const float4*>(&sm[OFF_W22T + k * 128 + ot4]);
                    float w1a[4] = {w1.x, w1.y, w1.z, w1.w};
                    float w2a[4] = {w2.x, w2.y, w2.z, w2.w};
                    #pragma unroll
                    for (int o = 0; o < 4; ++o) {
                        u64 d1 = dup2(w1a[o]);
                        u64 d2 = dup2(w2a[o]);
                        A1[o * 4 + 0] = fma2(d1, yA.x, A1[o * 4 + 0]);
                        A2[o * 4 + 0] = fma2(d2, yA.x, A2[o * 4 + 0]);
                        A1[o * 4 + 1] = fma2(d1, yA.y, A1[o * 4 + 1]);
                        A2[o * 4 + 1] = fma2(d2, yA.y, A2[o * 4 + 1]);
                        A1[o * 4 + 2] = fma2(d1, yB.x, A1[o * 4 + 2]);
                        A2[o * 4 + 2] = fma2(d2, yB.x, A2[o * 4 + 2]);
                        A1[o * 4 + 3] = fma2(d1, yB.y, A1[o * 4 + 3]);
                        A2[o * 4 + 3] = fma2(d2, yB.y, A2[o * 4 + 3]);
                    }
                }

                // epilogue: head dot, warp-reduce over the 32 o-tiles
                float part[8] = {0.f, 0.f, 0.f, 0.f, 0.f, 0.f, 0.f, 0.f};
                #pragma unroll
                for (int o = 0; o < 4; ++o) {
                    int og = ot4 + o;
                    float bo1 = sm[OFF_B12 + og], bo2 = sm[OFF_B22 + og], wo = sm[OFF_WOUT + og];
                    #pragma unroll
                    for (int sp = 0; sp < 4; ++sp) {
                        float u1l, u1h, u2l, u2h;
                        unpack2(A1[o * 4 + sp], u1l, u1h);
                        unpack2(A2[o * 4 + sp], u2l, u2h);
                        part[sp * 2]     = fmaf(wo, (u1l + bo1) * (u2l + bo2), part[sp * 2]);
                        part[sp * 2 + 1] = fmaf(wo, (u1h + bo1) * (u2h + bo2), part[sp * 2 + 1]);
                    }
                }
                #pragma unroll
                for (int i = 0; i < 8; ++i) {
                    #pragma unroll
                    for (int m = 16; m > 0; m >>= 1)
                        part[i] += __shfl_xor_sync(0xffffffffu, part[i], m);
                }
                if ((tid & 31) == 0) {
                    #pragma unroll
                    for (int i = 0; i < 8; ++i)
                        out[obase + sbase + s0 + i] = part[i];
                }
            }
            __syncthreads();
        } else {
            // =================== l unit: forward + JVP (64 samples) ===================
            const int sbase = (u - 512) * 64;

            // ---- phase 1: layer 1 -> y, yd in shared [k][64], 8 threads/sample ----
            {
                const int s = tid & 63;
                const int p = tid >> 6;              // 0..7, 16 rows each
                const float* xp = L    + (size_t)(sbase + s) * 8;
                const float* dp = Ldot + (size_t)(sbase + s) * 8;
                ulonglong2 xa = *reinterpret_cast<const ulonglong2*>(xp);
                ulonglong2 xb = *reinterpret_cast<const ulonglong2*>(xp + 4);
                ulonglong2 da = *reinterpret_cast<const ulonglong2*>(dp);
                ulonglong2 db = *reinterpret_cast<const ulonglong2*>(dp + 4);
                #pragma unroll
                for (int j = 0; j < 16; ++j) {
                    int r = p * 16 + j;
                    const ulonglong2* ra = reinterpret_cast<const ulonglong2*>(&sm[OFF_W11 + r * 8]);
                    const ulonglong2* rc = reinterpret_cast<const ulonglong2*>(&sm[OFF_W21 + r * 8]);
                    ulonglong2 q0 = ra[0], q1 = ra[1];
                    ulonglong2 m0 = rc[0], m1 = rc[1];
                    float z1  = dot8(q0, q1, xa, xb) + sm[OFF_B11 + r];
                    float z2  = dot8(m0, m1, xa, xb) + sm[OFF_B21 + r];
                    float z1d = dot8(q0, q1, da, db);
                    float z2d = dot8(m0, m1, da, db);
                    sm[OFF_Y  + r * 64 + s] = z1 * z2;
                    sm[OFF_YD + r * 64 + s] = fmaf(z1d, z2, z1 * z2d);
                }
            }
            __syncthreads();

            // ---- phase 2: 4 GEMM accum sets, tile = 8 samples x 2 outputs ----
            {
                const int ot = tid & 63;             // o-tile (2 outputs)
                const int st = tid >> 6;             // s-tile (8 samples)
                const int s0 = st * 8;
                const int ot2 = ot * 2;

                u64 C1[8], C2[8], E1[8], E2[8];
                #pragma unroll
                for (int i = 0; i < 8; ++i) { C1[i] = 0; C2[i] = 0; E1[i] = 0; E2[i] = 0; }

                #pragma unroll 2
                for (int k = 0; k < 128; ++k) {
                    ulonglong2 yA = *reinterpret_cast<const ulonglong2*>(&sm[OFF_Y  + k * 64 + s0]);
                    ulonglong2 yB = *reinterpret_cast<const ulonglong2*>(&sm[OFF_Y  + k * 64 + s0 + 4]);
                    ulonglong2 gA = *reinterpret_cast<const ulonglong2*>(&sm[OFF_YD + k * 64 + s0]);
                    ulonglong2 gB = *reinterpret_cast<const ulonglong2*>(&sm[OFF_YD + k * 64 + s0 + 4]);
                    float2 w1 = *reinterpret_cast<const float2*>(&sm[OFF_W12T + k * 128 + ot2]);
                    float2 w2 = *reinterpret_cast<const float2*>(&sm[OFF_W22T + k * 128 + ot2]);
                    float w1a[2] = {w1.x, w1.y};
                    float w2a[2] = {w2.x, w2.y};
                    #pragma unroll
                    for (int o = 0; o < 2; ++o) {
                        u64 d1 = dup2(w1a[o]);
                        u64 d2 = dup2(w2a[o]);
                        C1[o * 4 + 0] = fma2(d1, yA.x, C1[o * 4 + 0]);
                        C2[o * 4 + 0] = fma2(d2, yA.x, C2[o * 4 + 0]);
                        E1[o * 4 + 0] = fma2(d1, gA.x, E1[o * 4 + 0]);
                        E2[o * 4 + 0] = fma2(d2, gA.x, E2[o * 4 + 0]);
                        C1[o * 4 + 1] = fma2(d1, yA.y, C1[o * 4 + 1]);
                        C2[o * 4 + 1] = fma2(d2, yA.y, C2[o * 4 + 1]);
                        E1[o * 4 + 1] = fma2(d1, gA.y, E1[o * 4 + 1]);
                        E2[o * 4 + 1] = fma2(d2, gA.y, E2[o * 4 + 1]);
                        C1[o * 4 + 2] = fma2(d1, yB.x, C1[o * 4 + 2]);
                        C2[o * 4 + 2] = fma2(d2, yB.x, C2[o * 4 + 2]);
                        E1[o * 4 + 2] = fma2(d1, gB.x, E1[o * 4 + 2]);
                        E2[o * 4 + 2] = fma2(d2, gB.x, E2[o * 4 + 2]);
                        C1[o * 4 + 3] = fma2(d1, yB.y, C1[o * 4 + 3]);
                        C2[o * 4 + 3] = fma2(d2, yB.y, C2[o * 4 + 3]);
                        E1[o * 4 + 3] = fma2(d1, gB.y, E1[o * 4 + 3]);
                        E2[o * 4 + 3] = fma2(d2, gB.y, E2[o * 4 + 3]);
                    }
                }

                float vp[8] = {0.f, 0.f, 0.f, 0.f, 0.f, 0.f, 0.f, 0.f};
                float gp[8] = {0.f, 0.f, 0.f, 0.f, 0.f, 0.f, 0.f, 0.f};
                #pragma unroll
                for (int o = 0; o < 2; ++o) {
                    int og = ot2 + o;
                    float bo1 = sm[OFF_B12 + og], bo2 = sm[OFF_B22 + og], wo = sm[OFF_WOUT + og];
                    #pragma unroll
                    for (int sp = 0; sp < 4; ++sp) {
                        float u1l, u1h, u2l, u2h, d1l, d1h, d2l, d2h;
                        unpack2(C1[o * 4 + sp], u1l, u1h);
                        unpack2(C2[o * 4 + sp], u2l, u2h);
                        unpack2(E1[o * 4 + sp], d1l, d1h);
                        unpack2(E2[o * 4 + sp], d2l, d2h);
                        float a1l = u1l + bo1, a2l = u2l + bo2;
                        float a1h = u1h + bo1, a2h = u2h + bo2;
                        vp[sp * 2]     = fmaf(wo, a1l * a2l, vp[sp * 2]);
                        gp[sp * 2]     = fmaf(wo, fmaf(d1l, a2l, a1l * d2l), gp[sp * 2]);
                        vp[sp * 2 + 1] = fmaf(wo, a1h * a2h, vp[sp * 2 + 1]);
                        gp[sp * 2 + 1] = fmaf(wo, fmaf(d1h, a2h, a1h * d2h), gp[sp * 2 + 1]);
                    }
                }
                #pragma unroll
                for (int i = 0; i < 8; ++i) {
                    #pragma unroll
                    for (int m = 16; m > 0; m >>= 1) {
                        vp[i] += __shfl_xor_sync(0xffffffffu, vp[i], m);
                        gp[i] += __shfl_xor_sync(0xffffffffu, gp[i], m);
                    }
                }
                // two warps share each s-tile: stage per-warp sums, then combine
                if ((tid & 31) == 0) {
                    int half = (tid >> 5) & 1;       // which o-half this warp covered
                    float* scr = &sm[OFF_SCR + half * 128 + st * 16];
                    #pragma unroll
                    for (int i = 0; i < 8; ++i) { scr[i] = vp[i]; scr[8 + i] = gp[i]; }
                }
            }
            __syncthreads();
            if (tid < 128) {
                int st2 = tid >> 4, i = tid & 15;
                float v = sm[OFF_SCR + st2 * 16 + i] + sm[OFF_SCR + 128 + st2 * 16 + i];
                int sample = sbase + st2 * 8 + (i & 7);
                out[(i < 8 ? 65536 : 131072) + sample] = v;
            }
            __syncthreads();
        }
    }
}

extern "C" void kernel_launch(void* const* d_in, const int* in_sizes, int n_in,
                              void* d_out, int out_size)
{
    const float* T    = (const float*)d_in[0];
    const float* L    = (const float*)d_in[1];
    const float* Ldot = (const float*)d_in[2];
    const float* C    = (const float*)d_in[3];
    const float* w11  = (const float*)d_in[4];
    const float* b11  = (const float*)d_in[5];
    const float* w21  = (const float*)d_in[6];
    const float* b21  = (const float*)d_in[7];
    const float* w12  = (const float*)d_in[8];
    const float* b12  = (const float*)d_in[9];
    const float* w22  = (const float*)d_in[10];
    const float* b22  = (const float*)d_in[11];
    const float* wout = (const float*)d_in[12];
    float* out = (float*)d_out;

    cudaFuncSetAttribute(net_kernel, cudaFuncAttributeMaxDynamicSharedMemorySize, SMEM_BYTES);

    net_kernel<<<NBLOCKS, TPB, SMEM_BYTES>>>(T, L, Ldot, C,
                                             w11, b11, w21, b21,
                                             w12, b12, w22, b22,
                                             wout, out);
}